// round 8
// baseline (speedup 1.0000x reference)
#include <cuda_runtime.h>
#include <cuda_bf16.h>
#include <math.h>
#include <stdint.h>

// Problem constants: B=2, L=256, d_e=d_h=512
#define DH   512
#define LSEQ 256
#define MTOT 512   // B*L rows

// ---------------- scratch (no allocations allowed) ----------------
__device__ __align__(16) float g_rep  [MTOT*DH];
__device__ __align__(16) float g_dep2 [MTOT*DH];   // (dep + w1_b + b_logit) * KC
__device__ __align__(16) float g_head2[MTOT*DH];   // (head + w2_b) * KC
__device__ __align__(16) float g_gate1[MTOT*DH];   // rep @ wf1
__device__ __align__(16) float g_attn [MTOT*DH];

// bf16 split operands
__device__ __align__(16) __nv_bfloat16 g_Wthi[5 * DH * DH];  // W^T hi, [N,K] K-major
__device__ __align__(16) __nv_bfloat16 g_Wtlo[5 * DH * DH];
__device__ __align__(16) __nv_bfloat16 g_xhi[MTOT * DH];     // x split (gemm0 A)
__device__ __align__(16) __nv_bfloat16 g_xlo[MTOT * DH];
__device__ __align__(16) __nv_bfloat16 g_Ahi[MTOT * DH];     // rep split, then attn split
__device__ __align__(16) __nv_bfloat16 g_Alo[MTOT * DH];

// ---------------- math helpers ----------------
__device__ __forceinline__ float ex2f(float x) {
    float r; asm("ex2.approx.f32 %0, %1;" : "=f"(r) : "f"(x)); return r;
}
__device__ __forceinline__ float rcpf(float x) {
    float r; asm("rcp.approx.f32 %0, %1;" : "=f"(r) : "f"(x)); return r;
}
#define KCNST  (-0.57707801635558536f)   // -2*log2e/5
#define C2CNST (7.2134752044448170f)     // 5*log2e
#define TWOC2  (14.426950408889634f)

__device__ __forceinline__ void split_bf16(float v, __nv_bfloat16 &hi, __nv_bfloat16 &lo) {
    hi = __float2bfloat16(v);
    lo = __float2bfloat16(v - __bfloat162float(hi));
}

// ---------------- cp.async + mma.sync + ldmatrix (sm_80 path) ----------
__device__ __forceinline__ uint32_t smem_u32(const void* p) {
    uint32_t a;
    asm("{ .reg .u64 t; cvta.to.shared.u64 t, %1; cvt.u32.u64 %0, t; }" : "=r"(a) : "l"(p));
    return a;
}
__device__ __forceinline__ void cp_async16(uint32_t saddr, const void* g) {
    asm volatile("cp.async.cg.shared.global [%0], [%1], 16;" :: "r"(saddr), "l"(g) : "memory");
}
__device__ __forceinline__ void cp_commit() {
    asm volatile("cp.async.commit_group;" ::: "memory");
}
__device__ __forceinline__ void cp_wait0() {
    asm volatile("cp.async.wait_group 0;" ::: "memory");
}
__device__ __forceinline__ void ldm_x4(uint32_t* r, uint32_t a) {
    asm volatile("ldmatrix.sync.aligned.m8n8.x4.shared.b16 {%0,%1,%2,%3}, [%4];"
                 : "=r"(r[0]), "=r"(r[1]), "=r"(r[2]), "=r"(r[3]) : "r"(a));
}
// m16n8k16 row.col bf16 -> f32 accumulate
__device__ __forceinline__ void mma_bf16(float* d, const uint32_t* a, const uint32_t* b) {
    asm volatile(
        "mma.sync.aligned.m16n8k16.row.col.f32.bf16.bf16.f32 "
        "{%0,%1,%2,%3}, {%4,%5,%6,%7}, {%8,%9}, {%0,%1,%2,%3};"
        : "+f"(d[0]), "+f"(d[1]), "+f"(d[2]), "+f"(d[3])
        : "r"(a[0]), "r"(a[1]), "r"(a[2]), "r"(a[3]), "r"(b[0]), "r"(b[1]));
}

// =====================================================================
// Pre-pass: transpose + bf16-split the 5 weights.
// W [K=512, N=512] fp32 row-major -> Wt_hi/lo [N, K] bf16 K-major.
// =====================================================================
__global__ void __launch_bounds__(256) transpose_split_w(
    const float* __restrict__ w0, const float* __restrict__ w1,
    const float* __restrict__ w2, const float* __restrict__ w3,
    const float* __restrict__ w4)
{
    __shared__ float t[32][33];
    const int z = blockIdx.z;
    const float* W = (z == 0) ? w0 : (z == 1) ? w1 : (z == 2) ? w2 : (z == 3) ? w3 : w4;
    const int bi = blockIdx.x;   // k tile
    const int bj = blockIdx.y;   // n tile
    const int r  = threadIdx.x >> 3;
    const int c4 = (threadIdx.x & 7) * 4;

    const float4 v = *(const float4*)&W[(bi * 32 + r) * DH + bj * 32 + c4];
    t[r][c4 + 0] = v.x; t[r][c4 + 1] = v.y; t[r][c4 + 2] = v.z; t[r][c4 + 3] = v.w;
    __syncthreads();

    const size_t base = (size_t)z * DH * DH + (size_t)(bj * 32 + r) * DH + bi * 32 + c4;
    #pragma unroll
    for (int i = 0; i < 4; ++i) {
        const float a = t[c4 + i][r];
        __nv_bfloat16 hi, lo; split_bf16(a, hi, lo);
        g_Wthi[base + i] = hi;
        g_Wtlo[base + i] = lo;
    }
}

// Pre-pass: split x -> g_xhi/g_xlo.
__global__ void __launch_bounds__(256) split_x_kernel(const float* __restrict__ x)
{
    const int i = blockIdx.x * 256 + threadIdx.x;   // float4 index
    const float4 v = *(const float4*)&x[(size_t)i * 4];
    __nv_bfloat16 h0, l0, h1, l1, h2, l2, h3, l3;
    split_bf16(v.x, h0, l0); split_bf16(v.y, h1, l1);
    split_bf16(v.z, h2, l2); split_bf16(v.w, h3, l3);
    const size_t o = (size_t)i * 4;
    g_xhi[o] = h0; g_xhi[o+1] = h1; g_xhi[o+2] = h2; g_xhi[o+3] = h3;
    g_xlo[o] = l0; g_xlo[o+1] = l1; g_xlo[o+2] = l2; g_xlo[o+3] = l3;
}

// =====================================================================
// mma.sync GEMM: CTA tile 64x64, 8 warps (warp tile 32x16 = 2x2 atoms),
// K=512 in 8 chunks of 64, double-buffered cp.async, ldmatrix fragments.
// Split-bf16 3-pass: hi*hi + hi*lo + lo*hi, fp32 accumulators.
// MODE 0: A=x split,    B=Wt[0](fc),   epi: elu -> g_rep + split
// MODE 1: A=rep split,  B=Wt[1..3],    epi -> g_dep2/g_head2/g_gate1
// MODE 2: A=attn split, B=Wt[4](wf2),  epi: gate fusion -> dout
// =====================================================================
#define SROW 72                    // smem row stride in bf16 (bank padding)
#define ARRB (64 * SROW * 2)       // 9216 bytes per array
#define BUFB (4 * ARRB)            // 36864 bytes per buffer
#define SMTOT (2 * BUFB)           // 73728

template<int MODE>
__global__ void __launch_bounds__(256) gemm_mma(
    const float* __restrict__ b0v, const float* __restrict__ b1v,
    const float* __restrict__ b2v, float* __restrict__ dout)
{
    extern __shared__ char sm[];
    const uint32_t sbase = smem_u32(sm);
    const int tid  = threadIdx.x;
    const int warp = tid >> 5, lane = tid & 31;
    const int grp  = lane >> 2, tig = lane & 3;
    const int wm   = (warp >> 2) * 32;        // warp M offset (0/32)
    const int wn   = (warp & 3) * 16;         // warp N offset (0/16/32/48)

    const int m0 = blockIdx.x * 64;
    int n0, widx, region = 0;
    if (MODE == 1) { region = blockIdx.y >> 3; n0 = (blockIdx.y & 7) * 64; widx = 1 + region; }
    else           { n0 = blockIdx.y * 64; widx = (MODE == 0) ? 0 : 4; }

    const __nv_bfloat16* __restrict__ Ah = (MODE == 0) ? g_xhi : g_Ahi;
    const __nv_bfloat16* __restrict__ Al = (MODE == 0) ? g_xlo : g_Alo;
    const __nv_bfloat16* __restrict__ Bh = g_Wthi + (size_t)widx * DH * DH;
    const __nv_bfloat16* __restrict__ Bl = g_Wtlo + (size_t)widx * DH * DH;

    // ---- async loader: chunk c (64 k) into buffer buf. 2048 x 16B. ----
    auto issue = [&](int c, int buf) {
        #pragma unroll
        for (int i = 0; i < 8; ++i) {
            const int idx = tid + i * 256;       // 0..2047
            const int arr = idx >> 9;            // 0:Ah 1:Al 2:Bh 3:Bl
            const int row = (idx >> 3) & 63;
            const int kv  = (idx & 7) * 8;
            const __nv_bfloat16* gp =
                (arr == 0 ? Ah : arr == 1 ? Al : arr == 2 ? Bh : Bl)
                + (size_t)((arr < 2 ? m0 : n0) + row) * DH + c * 64 + kv;
            const uint32_t sa = sbase + buf * BUFB + arr * ARRB + row * (SROW * 2) + kv * 2;
            cp_async16(sa, gp);
        }
        cp_commit();
    };

    // ldmatrix per-lane address offsets (within one array)
    const int lr = (lane & 7) + ((lane >> 3) & 1) * 8;   // row within 16
    const int lk = ((lane >> 4) & 1) * 8;                // k-half within 16
    const uint32_t aoff0 = (uint32_t)((wm + lr) * SROW + lk) * 2;
    const uint32_t aoff1 = aoff0 + 16 * SROW * 2;
    const uint32_t boff  = (uint32_t)((wn + lr) * SROW + lk) * 2;

    float acc[2][2][4] = {};   // [matom][natom][reg]

    auto compute = [&](int buf) {
        const uint32_t base = sbase + buf * BUFB;
        #pragma unroll
        for (int ks = 0; ks < 4; ++ks) {
            const uint32_t ko = ks * 32;          // 16 bf16 = 32 bytes
            uint32_t Ah0[4], Ah1[4], Al0[4], Al1[4], Bh4[4], Bl4[4];
            ldm_x4(Ah0, base + aoff0 + ko);
            ldm_x4(Ah1, base + aoff1 + ko);
            ldm_x4(Al0, base + ARRB + aoff0 + ko);
            ldm_x4(Al1, base + ARRB + aoff1 + ko);
            ldm_x4(Bh4, base + 2 * ARRB + boff + ko);
            ldm_x4(Bl4, base + 3 * ARRB + boff + ko);
            uint32_t bh0[2] = {Bh4[0], Bh4[2]}, bh1[2] = {Bh4[1], Bh4[3]};
            uint32_t bl0[2] = {Bl4[0], Bl4[2]}, bl1[2] = {Bl4[1], Bl4[3]};
            mma_bf16(acc[0][0], Ah0, bh0); mma_bf16(acc[0][0], Ah0, bl0); mma_bf16(acc[0][0], Al0, bh0);
            mma_bf16(acc[0][1], Ah0, bh1); mma_bf16(acc[0][1], Ah0, bl1); mma_bf16(acc[0][1], Al0, bh1);
            mma_bf16(acc[1][0], Ah1, bh0); mma_bf16(acc[1][0], Ah1, bl0); mma_bf16(acc[1][0], Al1, bh0);
            mma_bf16(acc[1][1], Ah1, bh1); mma_bf16(acc[1][1], Ah1, bl1); mma_bf16(acc[1][1], Al1, bh1);
        }
    };

    // ---- pipelined K loop ----
    issue(0, 0);
    cp_wait0();
    __syncthreads();
    #pragma unroll 1
    for (int c = 0; c < 8; ++c) {
        if (c < 7) issue(c + 1, (c + 1) & 1);
        compute(c & 1);
        if (c < 7) { cp_wait0(); __syncthreads(); }
    }

    // ---- fused epilogue ----
    #pragma unroll
    for (int ma = 0; ma < 2; ++ma) {
        #pragma unroll
        for (int nb = 0; nb < 2; ++nb) {
            const float* d = acc[ma][nb];
            const int col = n0 + wn + nb * 8 + 2 * tig;
            #pragma unroll
            for (int half = 0; half < 2; ++half) {
                const int row = m0 + wm + ma * 16 + grp + half * 8;
                const float v0 = d[half * 2 + 0];
                const float v1 = d[half * 2 + 1];
                const size_t idx = (size_t)row * DH + col;
                if (MODE == 0) {
                    const float s0 = v0 + b0v[col], s1 = v1 + b0v[col + 1];
                    const float r0 = s0 > 0.f ? s0 : expm1f(s0);
                    const float r1 = s1 > 0.f ? s1 : expm1f(s1);
                    g_rep[idx] = r0; g_rep[idx + 1] = r1;
                    __nv_bfloat16 h, l;
                    split_bf16(r0, h, l); g_Ahi[idx]     = h; g_Alo[idx]     = l;
                    split_bf16(r1, h, l); g_Ahi[idx + 1] = h; g_Alo[idx + 1] = l;
                } else if (MODE == 1) {
                    if (region == 0) {
                        g_dep2[idx]     = (v0 + b0v[col]     + b2v[col])     * KCNST;
                        g_dep2[idx + 1] = (v1 + b0v[col + 1] + b2v[col + 1]) * KCNST;
                    } else if (region == 1) {
                        g_head2[idx]     = (v0 + b1v[col])     * KCNST;
                        g_head2[idx + 1] = (v1 + b1v[col + 1]) * KCNST;
                    } else {
                        g_gate1[idx] = v0; g_gate1[idx + 1] = v1;
                    }
                } else {
                    const float z0 = g_gate1[idx]     + v0 + b0v[col];
                    const float z1 = g_gate1[idx + 1] + v1 + b0v[col + 1];
                    const float gg0 = 1.f / (1.f + expf(-z0));
                    const float gg1 = 1.f / (1.f + expf(-z1));
                    const float a0 = g_attn[idx], a1 = g_attn[idx + 1];
                    dout[idx]     = fmaf(gg0, g_rep[idx]     - a0, a0);
                    dout[idx + 1] = fmaf(gg1, g_rep[idx + 1] - a1, a1);
                }
            }
        }
    }
}

// =====================================================================
// Fused masked tanh-logit softmax + weighted sum over dependents.
// grid (2*65, 2): blockIdx.x -> (batch, group q), blockIdx.y -> channel half.
// q<63: 4 rows {2q, 2q+1, 253-2q, 254-2q} share each (dep, rep) load; the
//   wfun count per thread is exactly 512 for every q (perfect balance).
// q=63: rows {126,127,128}.  q=64: row 255, FULLY masked: reference's
//   logits+(-1e9) round to exactly -1e9 in fp32 (ulp(1e9)=64 >> |C*tanh|<=5)
//   -> softmax exactly uniform -> attn = mean_j rep[j].
// Writes g_attn fp32 AND bf16 split into g_Ahi/g_Alo (gemm2 A operand).
// =====================================================================
__device__ __forceinline__ float wfun(float x) {
    const float t = ex2f(x);              // exp(-2u)
    const float r = rcpf(1.f + t);
    return ex2f(fmaf(TWOC2, r, -C2CNST)); // exp(C*tanh(u))
}
__device__ __forceinline__ void store_attn(int idx, float v) {
    g_attn[idx] = v;
    __nv_bfloat16 hi, lo; split_bf16(v, hi, lo);
    g_Ahi[idx] = hi; g_Alo[idx] = lo;
}

__global__ void __launch_bounds__(256) attn_kernel()
{
    const int cta = blockIdx.x;
    const int b = cta / 65;
    const int q = cta - b * 65;
    const int h = blockIdx.y * 256 + threadIdx.x;
    const int rb = b * LSEQ;

    const float* __restrict__ dep = g_dep2  + rb * DH;
    const float* __restrict__ hd  = g_head2 + rb * DH;
    const float* __restrict__ rp  = g_rep   + rb * DH;

    if (q == 64) {
        // Row 255: uniform mean over all j.
        float s = 0.f;
        #pragma unroll 8
        for (int j = 0; j < LSEQ; ++j)
            s += rp[j * DH + h];
        store_attn((rb + 255) * DH + h, s * (1.0f / 256.0f));
        return;
    }

    if (q == 63) {
        // rows 126, 127, 128
        const float h0 = hd[126 * DH + h];
        const float h1 = hd[127 * DH + h];
        const float h2 = hd[128 * DH + h];
        float n0 = 0.f, d0 = 0.f, n1 = 0.f, d1 = 0.f, n2 = 0.f, d2 = 0.f;
        {   // j = 127: row 126 only
            const float dj = dep[127 * DH + h], rj = rp[127 * DH + h];
            const float w = wfun(dj + h0); n0 = fmaf(w, rj, n0); d0 += w;
        }
        {   // j = 128: rows 126,127
            const float dj = dep[128 * DH + h], rj = rp[128 * DH + h];
            float w = wfun(dj + h0); n0 = fmaf(w, rj, n0); d0 += w;
            w = wfun(dj + h1); n1 = fmaf(w, rj, n1); d1 += w;
        }
        #pragma unroll 2
        for (int j = 129; j < 256; ++j) {
            const float dj = dep[j * DH + h], rj = rp[j * DH + h];
            float w = wfun(dj + h0); n0 = fmaf(w, rj, n0); d0 += w;
            w = wfun(dj + h1); n1 = fmaf(w, rj, n1); d1 += w;
            w = wfun(dj + h2); n2 = fmaf(w, rj, n2); d2 += w;
        }
        store_attn((rb + 126) * DH + h, n0 / d0);
        store_attn((rb + 127) * DH + h, n1 / d1);
        store_attn((rb + 128) * DH + h, n2 / d2);
        return;
    }

    // rows a=2q, a+1, c=253-2q, c+1
    const int ra = 2 * q, rc = 253 - 2 * q;
    const float ha0 = hd[ra * DH + h];
    const float ha1 = hd[(ra + 1) * DH + h];
    const float hc0 = hd[rc * DH + h];
    const float hc1 = hd[(rc + 1) * DH + h];

    float na0 = 0.f, da0 = 0.f, na1 = 0.f, da1 = 0.f;
    float nc0 = 0.f, dc0 = 0.f, nc1 = 0.f, dc1 = 0.f;

    {   // seg0: j = 2q+1 -> row a only
        const int j = ra + 1;
        const float dj = dep[j * DH + h], rj = rp[j * DH + h];
        const float w = wfun(dj + ha0); na0 = fmaf(w, rj, na0); da0 += w;
    }
    // seg1: j in [2q+2, 254-2q) -> rows a, a+1
    #pragma unroll 2
    for (int j = ra + 2; j < rc + 1; ++j) {
        const float dj = dep[j * DH + h], rj = rp[j * DH + h];
        float w = wfun(dj + ha0); na0 = fmaf(w, rj, na0); da0 += w;
        w = wfun(dj + ha1); na1 = fmaf(w, rj, na1); da1 += w;
    }
    {   // seg2: j = 254-2q -> rows a, a+1, c
        const int j = rc + 1;
        const float dj = dep[j * DH + h], rj = rp[j * DH + h];
        float w = wfun(dj + ha0); na0 = fmaf(w, rj, na0); da0 += w;
        w = wfun(dj + ha1); na1 = fmaf(w, rj, na1); da1 += w;
        w = wfun(dj + hc0); nc0 = fmaf(w, rj, nc0); dc0 += w;
    }
    // seg3: j in [255-2q, 256) -> all 4 rows
    #pragma unroll 2
    for (int j = rc + 2; j < 256; ++j) {
        const float dj = dep[j * DH + h], rj = rp[j * DH + h];
        float w = wfun(dj + ha0); na0 = fmaf(w, rj, na0); da0 += w;
        w = wfun(dj + ha1); na1 = fmaf(w, rj, na1); da1 += w;
        w = wfun(dj + hc0); nc0 = fmaf(w, rj, nc0); dc0 += w;
        w = wfun(dj + hc1); nc1 = fmaf(w, rj, nc1); dc1 += w;
    }
    store_attn((rb + ra)     * DH + h, na0 / da0);
    store_attn((rb + ra + 1) * DH + h, na1 / da1);
    store_attn((rb + rc)     * DH + h, nc0 / dc0);
    store_attn((rb + rc + 1) * DH + h, nc1 / dc1);
}

// =====================================================================
extern "C" void kernel_launch(void* const* d_in, const int* in_sizes, int n_in,
                              void* d_out, int out_size)
{
    const float* x       = (const float*)d_in[0];
    const float* fc_w    = (const float*)d_in[1];
    const float* fc_b    = (const float*)d_in[2];
    const float* w1_w    = (const float*)d_in[3];
    const float* w1_b    = (const float*)d_in[4];
    const float* w2_w    = (const float*)d_in[5];
    const float* w2_b    = (const float*)d_in[6];
    const float* b_logit = (const float*)d_in[7];
    const float* wf1_w   = (const float*)d_in[8];
    const float* wf2_w   = (const float*)d_in[9];
    const float* bf      = (const float*)d_in[10];
    float* out = (float*)d_out;

    cudaFuncSetAttribute(gemm_mma<0>, cudaFuncAttributeMaxDynamicSharedMemorySize, SMTOT);
    cudaFuncSetAttribute(gemm_mma<1>, cudaFuncAttributeMaxDynamicSharedMemorySize, SMTOT);
    cudaFuncSetAttribute(gemm_mma<2>, cudaFuncAttributeMaxDynamicSharedMemorySize, SMTOT);

    // 0) weight transpose+split and x split
    transpose_split_w<<<dim3(16, 16, 5), 256>>>(fc_w, w1_w, w2_w, wf1_w, wf2_w);
    split_x_kernel<<<256, 256>>>(x);
    // 1) rep = elu(x @ fc_w + fc_b)   (+ bf16 split of rep)
    gemm_mma<0><<<dim3(8, 8), 256, SMTOT>>>(fc_b, nullptr, nullptr, nullptr);
    // 2) dep2/head2/gate1 = rep @ {w1,w2,wf1}
    gemm_mma<1><<<dim3(8, 24), 256, SMTOT>>>(w1_b, w2_b, b_logit, nullptr);
    // 3) fused masked softmax attention (+ bf16 split of attn)
    attn_kernel<<<dim3(2 * 65, 2), 256>>>();
    // 4) out = sigmoid(gate1 + attn@wf2 + bf) * rep + (1-g) * attn
    gemm_mma<2><<<dim3(8, 8), 256, SMTOT>>>(bf, nullptr, nullptr, out);
}

// round 9
// speedup vs baseline: 1.6273x; 1.6273x over previous
#include <cuda_runtime.h>
#include <cuda_bf16.h>
#include <math.h>
#include <stdint.h>

// Problem constants: B=2, L=256, d_e=d_h=512
#define DH   512
#define LSEQ 256
#define MTOT 512   // B*L rows

// ---------------- scratch (no allocations allowed) ----------------
__device__ __align__(16) float g_rep  [MTOT*DH];
__device__ __align__(16) float g_dep2 [MTOT*DH];   // (dep + w1_b + b_logit) * KC
__device__ __align__(16) float g_head2[MTOT*DH];   // (head + w2_b) * KC
__device__ __align__(16) float g_gate1[MTOT*DH];   // rep @ wf1
__device__ __align__(16) float g_attn [MTOT*DH];

// bf16 split operands
__device__ __align__(16) __nv_bfloat16 g_Wthi[5 * DH * DH];  // W^T hi, [N,K] K-major
__device__ __align__(16) __nv_bfloat16 g_Wtlo[5 * DH * DH];
__device__ __align__(16) __nv_bfloat16 g_xhi[MTOT * DH];     // x split (gemm0 A)
__device__ __align__(16) __nv_bfloat16 g_xlo[MTOT * DH];
__device__ __align__(16) __nv_bfloat16 g_Ahi[MTOT * DH];     // rep split, then attn split
__device__ __align__(16) __nv_bfloat16 g_Alo[MTOT * DH];

// ---------------- math helpers ----------------
__device__ __forceinline__ float ex2f(float x) {
    float r; asm("ex2.approx.f32 %0, %1;" : "=f"(r) : "f"(x)); return r;
}
__device__ __forceinline__ float rcpf(float x) {
    float r; asm("rcp.approx.f32 %0, %1;" : "=f"(r) : "f"(x)); return r;
}
#define KCNST  (-0.57707801635558536f)   // -2*log2e/5
#define C2CNST (7.2134752044448170f)     // 5*log2e
#define TWOC2  (14.426950408889634f)

__device__ __forceinline__ void split_bf16(float v, __nv_bfloat16 &hi, __nv_bfloat16 &lo) {
    hi = __float2bfloat16(v);
    lo = __float2bfloat16(v - __bfloat162float(hi));
}

// ---------------- cp.async + mma.sync (sm_80 path, legal on sm_100) ----
__device__ __forceinline__ uint32_t smem_u32(const void* p) {
    uint32_t a;
    asm("{ .reg .u64 t; cvta.to.shared.u64 t, %1; cvt.u32.u64 %0, t; }" : "=r"(a) : "l"(p));
    return a;
}
__device__ __forceinline__ void cp_async16(uint32_t saddr, const void* g) {
    asm volatile("cp.async.cg.shared.global [%0], [%1], 16;" :: "r"(saddr), "l"(g) : "memory");
}
__device__ __forceinline__ void cp_commit() {
    asm volatile("cp.async.commit_group;" ::: "memory");
}
__device__ __forceinline__ void cp_wait0() {
    asm volatile("cp.async.wait_group 0;" ::: "memory");
}
// m16n8k16 row.col bf16 -> f32 accumulate
__device__ __forceinline__ void mma_bf16(float* d, const uint32_t* a, const uint32_t* b) {
    asm volatile(
        "mma.sync.aligned.m16n8k16.row.col.f32.bf16.bf16.f32 "
        "{%0,%1,%2,%3}, {%4,%5,%6,%7}, {%8,%9}, {%0,%1,%2,%3};"
        : "+f"(d[0]), "+f"(d[1]), "+f"(d[2]), "+f"(d[3])
        : "r"(a[0]), "r"(a[1]), "r"(a[2]), "r"(a[3]), "r"(b[0]), "r"(b[1]));
}

// =====================================================================
// Pre-pass: transpose + bf16-split the 5 weights.
// W [K=512, N=512] fp32 row-major -> Wt_hi/lo [N, K] bf16 K-major.
// =====================================================================
__global__ void __launch_bounds__(256) transpose_split_w(
    const float* __restrict__ w0, const float* __restrict__ w1,
    const float* __restrict__ w2, const float* __restrict__ w3,
    const float* __restrict__ w4)
{
    __shared__ float t[32][33];
    const int z = blockIdx.z;
    const float* W = (z == 0) ? w0 : (z == 1) ? w1 : (z == 2) ? w2 : (z == 3) ? w3 : w4;
    const int bi = blockIdx.x;   // k tile
    const int bj = blockIdx.y;   // n tile
    const int r  = threadIdx.x >> 3;
    const int c4 = (threadIdx.x & 7) * 4;

    const float4 v = *(const float4*)&W[(bi * 32 + r) * DH + bj * 32 + c4];
    t[r][c4 + 0] = v.x; t[r][c4 + 1] = v.y; t[r][c4 + 2] = v.z; t[r][c4 + 3] = v.w;
    __syncthreads();

    const size_t base = (size_t)z * DH * DH + (size_t)(bj * 32 + r) * DH + bi * 32 + c4;
    #pragma unroll
    for (int i = 0; i < 4; ++i) {
        const float a = t[c4 + i][r];
        __nv_bfloat16 hi, lo; split_bf16(a, hi, lo);
        g_Wthi[base + i] = hi;
        g_Wtlo[base + i] = lo;
    }
}

// Pre-pass: split x -> g_xhi/g_xlo.
__global__ void __launch_bounds__(256) split_x_kernel(const float* __restrict__ x)
{
    const int i = blockIdx.x * 256 + threadIdx.x;   // float4 index
    const float4 v = *(const float4*)&x[(size_t)i * 4];
    __nv_bfloat16 h0, l0, h1, l1, h2, l2, h3, l3;
    split_bf16(v.x, h0, l0); split_bf16(v.y, h1, l1);
    split_bf16(v.z, h2, l2); split_bf16(v.w, h3, l3);
    const size_t o = (size_t)i * 4;
    g_xhi[o] = h0; g_xhi[o+1] = h1; g_xhi[o+2] = h2; g_xhi[o+3] = h3;
    g_xlo[o] = l0; g_xlo[o+1] = l1; g_xlo[o+2] = l2; g_xlo[o+3] = l3;
}

// =====================================================================
// mma.sync GEMM: CTA tile 32 x TN (TN=64 mode1, TN=32 modes 0/2),
// 4 warps, warp tile 32 x (TN/4) = 2 x (TN/32) m16n8k16 atoms.
// K=512 in 8 chunks of 64, double-buffered cp.async, scalar LDS frags
// (the proven R7 inner loop, just fewer atoms -> more CTAs).
// Split-bf16 3-pass: hi*hi + hi*lo + lo*hi, fp32 accumulators.
// MODE 0: A=x split,    B=Wt[0](fc),   epi: elu -> g_rep + split
// MODE 1: A=rep split,  B=Wt[1..3],    epi -> g_dep2/g_head2/g_gate1
// MODE 2: A=attn split, B=Wt[4](wf2),  epi: gate fusion -> dout
// =====================================================================
#define SROW 72                    // smem row stride in bf16 (bank padding)
#define ROWB (SROW * 2)            // 144 bytes per row

template<int MODE, int TN>
__global__ void __launch_bounds__(128) gemm_mma(
    const float* __restrict__ b0v, const float* __restrict__ b1v,
    const float* __restrict__ b2v, float* __restrict__ dout)
{
    constexpr int NAT   = TN / 32;             // n atoms per warp (1 or 2)
    constexpr int ARR_A = 32 * ROWB;           // 4608 B
    constexpr int ARR_B = TN * ROWB;           // 4608 or 9216 B
    constexpr int OFF_AL = ARR_A;
    constexpr int OFF_BH = 2 * ARR_A;
    constexpr int OFF_BL = 2 * ARR_A + ARR_B;
    constexpr int BUFB   = 2 * ARR_A + 2 * ARR_B;
    constexpr int NTXN   = 512 + TN * 16;      // 16B txns per chunk (A:512, B:TN*16)

    extern __shared__ char sm[];
    const uint32_t sbase = smem_u32(sm);
    const int tid  = threadIdx.x;
    const int warp = tid >> 5, lane = tid & 31;
    const int grp  = lane >> 2, tig = lane & 3;
    const int wn   = warp * (TN / 4);          // warp N offset

    const int m0 = blockIdx.x * 32;
    int n0, widx, region = 0;
    if (MODE == 1) { region = blockIdx.y >> 3; n0 = (blockIdx.y & 7) * TN; widx = 1 + region; }
    else           { n0 = blockIdx.y * TN; widx = (MODE == 0) ? 0 : 4; }

    const __nv_bfloat16* __restrict__ Ah = (MODE == 0) ? g_xhi : g_Ahi;
    const __nv_bfloat16* __restrict__ Al = (MODE == 0) ? g_xlo : g_Alo;
    const __nv_bfloat16* __restrict__ Bh = g_Wthi + (size_t)widx * DH * DH;
    const __nv_bfloat16* __restrict__ Bl = g_Wtlo + (size_t)widx * DH * DH;

    // ---- async loader: chunk c (64 k) into buffer buf ----
    auto issue = [&](int c, int buf) {
        #pragma unroll
        for (int i = 0; i < NTXN / 128; ++i) {
            const int idx = tid + i * 128;
            const __nv_bfloat16* gp;
            uint32_t sa;
            if (idx < 512) {                       // A: Ah then Al, 256 txns each
                const int arr = idx >> 8;          // 0:Ah 1:Al
                const int row = (idx & 255) >> 3;
                const int kv  = (idx & 7) * 8;
                gp = (arr == 0 ? Ah : Al) + (size_t)(m0 + row) * DH + c * 64 + kv;
                sa = sbase + buf * BUFB + arr * OFF_AL + row * ROWB + kv * 2;
            } else {                               // B: Bh then Bl, TN*8 txns each
                const int j   = idx - 512;
                const int arr = j / (TN * 8);      // 0:Bh 1:Bl
                const int rj  = j - arr * (TN * 8);
                const int row = rj >> 3;
                const int kv  = (rj & 7) * 8;
                gp = (arr == 0 ? Bh : Bl) + (size_t)(n0 + row) * DH + c * 64 + kv;
                sa = sbase + buf * BUFB + (arr == 0 ? OFF_BH : OFF_BL) + row * ROWB + kv * 2;
            }
            cp_async16(sa, gp);
        }
        cp_commit();
    };

    float acc[2][NAT][4] = {};   // [matom][natom][reg]

    auto compute = [&](int buf) {
        const char* base = sm + buf * BUFB;
        const char* A0 = base;
        const char* A1 = base + OFF_AL;
        const char* B0 = base + OFF_BH;
        const char* B1 = base + OFF_BL;
        #pragma unroll
        for (int ks = 0; ks < 4; ++ks) {
            const int kb = ks * 16 + 2 * tig;
            uint32_t ah[2][4], al[2][4], bh[NAT][2], bl[NAT][2];
            #pragma unroll
            for (int ma = 0; ma < 2; ++ma) {
                const int r = ma * 16 + grp;
                ah[ma][0] = *(const uint32_t*)(A0 + r * ROWB + kb * 2);
                ah[ma][1] = *(const uint32_t*)(A0 + (r + 8) * ROWB + kb * 2);
                ah[ma][2] = *(const uint32_t*)(A0 + r * ROWB + (kb + 8) * 2);
                ah[ma][3] = *(const uint32_t*)(A0 + (r + 8) * ROWB + (kb + 8) * 2);
                al[ma][0] = *(const uint32_t*)(A1 + r * ROWB + kb * 2);
                al[ma][1] = *(const uint32_t*)(A1 + (r + 8) * ROWB + kb * 2);
                al[ma][2] = *(const uint32_t*)(A1 + r * ROWB + (kb + 8) * 2);
                al[ma][3] = *(const uint32_t*)(A1 + (r + 8) * ROWB + (kb + 8) * 2);
            }
            #pragma unroll
            for (int nb = 0; nb < NAT; ++nb) {
                const int r = wn + nb * 8 + grp;
                bh[nb][0] = *(const uint32_t*)(B0 + r * ROWB + kb * 2);
                bh[nb][1] = *(const uint32_t*)(B0 + r * ROWB + (kb + 8) * 2);
                bl[nb][0] = *(const uint32_t*)(B1 + r * ROWB + kb * 2);
                bl[nb][1] = *(const uint32_t*)(B1 + r * ROWB + (kb + 8) * 2);
            }
            #pragma unroll
            for (int ma = 0; ma < 2; ++ma)
                #pragma unroll
                for (int nb = 0; nb < NAT; ++nb) {
                    mma_bf16(acc[ma][nb], ah[ma], bh[nb]);
                    mma_bf16(acc[ma][nb], ah[ma], bl[nb]);
                    mma_bf16(acc[ma][nb], al[ma], bh[nb]);
                }
        }
    };

    // ---- pipelined K loop ----
    issue(0, 0);
    cp_wait0();
    __syncthreads();
    #pragma unroll 1
    for (int c = 0; c < 8; ++c) {
        if (c < 7) issue(c + 1, (c + 1) & 1);
        compute(c & 1);
        if (c < 7) { cp_wait0(); __syncthreads(); }
    }

    // ---- fused epilogue ----
    #pragma unroll
    for (int ma = 0; ma < 2; ++ma) {
        #pragma unroll
        for (int nb = 0; nb < NAT; ++nb) {
            const float* d = acc[ma][nb];
            const int col = n0 + wn + nb * 8 + 2 * tig;
            #pragma unroll
            for (int half = 0; half < 2; ++half) {
                const int row = m0 + ma * 16 + grp + half * 8;
                const float v0 = d[half * 2 + 0];
                const float v1 = d[half * 2 + 1];
                const size_t idx = (size_t)row * DH + col;
                if (MODE == 0) {
                    const float s0 = v0 + b0v[col], s1 = v1 + b0v[col + 1];
                    const float r0 = s0 > 0.f ? s0 : expm1f(s0);
                    const float r1 = s1 > 0.f ? s1 : expm1f(s1);
                    g_rep[idx] = r0; g_rep[idx + 1] = r1;
                    __nv_bfloat16 h, l;
                    split_bf16(r0, h, l); g_Ahi[idx]     = h; g_Alo[idx]     = l;
                    split_bf16(r1, h, l); g_Ahi[idx + 1] = h; g_Alo[idx + 1] = l;
                } else if (MODE == 1) {
                    if (region == 0) {
                        g_dep2[idx]     = (v0 + b0v[col]     + b2v[col])     * KCNST;
                        g_dep2[idx + 1] = (v1 + b0v[col + 1] + b2v[col + 1]) * KCNST;
                    } else if (region == 1) {
                        g_head2[idx]     = (v0 + b1v[col])     * KCNST;
                        g_head2[idx + 1] = (v1 + b1v[col + 1]) * KCNST;
                    } else {
                        g_gate1[idx] = v0; g_gate1[idx + 1] = v1;
                    }
                } else {
                    const float z0 = g_gate1[idx]     + v0 + b0v[col];
                    const float z1 = g_gate1[idx + 1] + v1 + b0v[col + 1];
                    const float gg0 = 1.f / (1.f + expf(-z0));
                    const float gg1 = 1.f / (1.f + expf(-z1));
                    const float a0 = g_attn[idx], a1 = g_attn[idx + 1];
                    dout[idx]     = fmaf(gg0, g_rep[idx]     - a0, a0);
                    dout[idx + 1] = fmaf(gg1, g_rep[idx + 1] - a1, a1);
                }
            }
        }
    }
}

#define SMTOT64 (2 * (2 * 32 * ROWB + 2 * 64 * ROWB))   // 55296
#define SMTOT32 (2 * (4 * 32 * ROWB))                   // 36864

// =====================================================================
// Fused masked tanh-logit softmax + weighted sum over dependents.
// (Reverted to the proven R7 version.)
// grid (258, 2): blockIdx.x -> (batch, pair p), blockIdx.y -> channel half.
// p<127: rows {p, 254-p} (work sums to 256, j-ranges nest). p=127: row 127.
// p=128: row 255, FULLY masked: reference's logits+(-1e9) round to exactly
//   -1e9 in fp32 (ulp(1e9)=64 >> |C*tanh|<=5) -> softmax exactly uniform
//   -> attn = mean_j rep[j].
// Writes g_attn fp32 AND bf16 split into g_Ahi/g_Alo (gemm2 A operand).
// =====================================================================
__device__ __forceinline__ float wfun(float x) {
    const float t = ex2f(x);              // exp(-2u)
    const float r = rcpf(1.f + t);
    return ex2f(fmaf(TWOC2, r, -C2CNST)); // exp(C*tanh(u))
}
__device__ __forceinline__ void store_attn(int idx, float v) {
    g_attn[idx] = v;
    __nv_bfloat16 hi, lo; split_bf16(v, hi, lo);
    g_Ahi[idx] = hi; g_Alo[idx] = lo;
}

__global__ void __launch_bounds__(256) attn_kernel()
{
    const int cta = blockIdx.x;
    const int b = cta / 129;
    const int p = cta - b * 129;
    const int h = blockIdx.y * 256 + threadIdx.x;

    const float* __restrict__ dep = g_dep2  + b * LSEQ * DH;
    const float* __restrict__ hd  = g_head2 + b * LSEQ * DH;
    const float* __restrict__ rp  = g_rep   + b * LSEQ * DH;

    if (p == 128) {
        float s = 0.f;
        #pragma unroll 8
        for (int j = 0; j < LSEQ; ++j)
            s += rp[j * DH + h];
        store_attn((b * LSEQ + 255) * DH + h, s * (1.0f / 256.0f));
        return;
    }

    int i1, i2, jstart, jmid;
    if (p < 127)       { i1 = p;   i2 = 254 - p; jstart = p + 1; jmid = 255 - p; }
    else               { i1 = 127; i2 = -1;      jstart = 128;   jmid = 256; }

    const float h1 = hd[i1 * DH + h];
    const float h2 = (i2 >= 0) ? hd[i2 * DH + h] : 0.f;

    float n1 = 0.f, d1 = 0.f, n2 = 0.f, d2 = 0.f;
    int j = jstart;
    #pragma unroll 4
    for (; j < jmid; ++j) {
        const float dj = dep[j * DH + h];
        const float rj = rp [j * DH + h];
        const float w  = wfun(dj + h1);
        n1 = fmaf(w, rj, n1); d1 += w;
    }
    #pragma unroll 4
    for (; j < 256; ++j) {
        const float dj = dep[j * DH + h];
        const float rj = rp [j * DH + h];
        const float wa = wfun(dj + h1);
        n1 = fmaf(wa, rj, n1); d1 += wa;
        const float wb = wfun(dj + h2);
        n2 = fmaf(wb, rj, n2); d2 += wb;
    }
    store_attn((b * LSEQ + i1) * DH + h, n1 / d1);
    if (i2 >= 0)
        store_attn((b * LSEQ + i2) * DH + h, n2 / d2);
}

// =====================================================================
extern "C" void kernel_launch(void* const* d_in, const int* in_sizes, int n_in,
                              void* d_out, int out_size)
{
    const float* x       = (const float*)d_in[0];
    const float* fc_w    = (const float*)d_in[1];
    const float* fc_b    = (const float*)d_in[2];
    const float* w1_w    = (const float*)d_in[3];
    const float* w1_b    = (const float*)d_in[4];
    const float* w2_w    = (const float*)d_in[5];
    const float* w2_b    = (const float*)d_in[6];
    const float* b_logit = (const float*)d_in[7];
    const float* wf1_w   = (const float*)d_in[8];
    const float* wf2_w   = (const float*)d_in[9];
    const float* bf      = (const float*)d_in[10];
    float* out = (float*)d_out;

    cudaFuncSetAttribute((const void*)gemm_mma<0,32>, cudaFuncAttributeMaxDynamicSharedMemorySize, SMTOT32);
    cudaFuncSetAttribute((const void*)gemm_mma<1,64>, cudaFuncAttributeMaxDynamicSharedMemorySize, SMTOT64);
    cudaFuncSetAttribute((const void*)gemm_mma<2,32>, cudaFuncAttributeMaxDynamicSharedMemorySize, SMTOT32);

    // 0) weight transpose+split and x split
    transpose_split_w<<<dim3(16, 16, 5), 256>>>(fc_w, w1_w, w2_w, wf1_w, wf2_w);
    split_x_kernel<<<256, 256>>>(x);
    // 1) rep = elu(x @ fc_w + fc_b)   (+ bf16 split of rep)  — 256 CTAs
    gemm_mma<0,32><<<dim3(16, 16), 128, SMTOT32>>>(fc_b, nullptr, nullptr, nullptr);
    // 2) dep2/head2/gate1 = rep @ {w1,w2,wf1}                — 384 CTAs
    gemm_mma<1,64><<<dim3(16, 24), 128, SMTOT64>>>(w1_b, w2_b, b_logit, nullptr);
    // 3) fused masked softmax attention (+ bf16 split of attn)
    attn_kernel<<<dim3(258, 2), 256>>>();
    // 4) out = sigmoid(gate1 + attn@wf2 + bf) * rep + (1-g) * attn — 256 CTAs
    gemm_mma<2,32><<<dim3(16, 16), 128, SMTOT32>>>(bf, nullptr, nullptr, out);
}